// round 15
// baseline (speedup 1.0000x reference)
#include <cuda_runtime.h>
#include <math.h>
#include <stdint.h>

#define N_NODES 12288
#define D_IN    512
#define HID     256
#define D_OUT   64
#define E_EDGES 393216

// ---------------- scratch (device globals: no runtime allocation) ----------
__device__ float  g_h0[(size_t)N_NODES * HID];
__device__ float  g_zn[(size_t)N_NODES * D_OUT];
__device__ double g_loss_sum;

// ---------------------------------------------------------------------------
// tf32 / cp.async / sigmoid / streaming-store helpers
// ---------------------------------------------------------------------------
__device__ __forceinline__ uint32_t f32_to_tf32(float x) {
    uint32_t r;
    asm("cvt.rna.tf32.f32 %0, %1;" : "=r"(r) : "f"(x));
    return r;
}

__device__ __forceinline__ void mma_tf32(float d[4],
                                         const uint32_t a[4],
                                         const uint32_t b[2]) {
    asm volatile(
        "mma.sync.aligned.m16n8k8.row.col.f32.tf32.tf32.f32 "
        "{%0,%1,%2,%3}, {%4,%5,%6,%7}, {%8,%9}, {%0,%1,%2,%3};"
        : "+f"(d[0]), "+f"(d[1]), "+f"(d[2]), "+f"(d[3])
        : "r"(a[0]), "r"(a[1]), "r"(a[2]), "r"(a[3]),
          "r"(b[0]), "r"(b[1]));
}

__device__ __forceinline__ void cp_async16(float* smem_dst, const float* gmem_src) {
    uint32_t s = (uint32_t)__cvta_generic_to_shared(smem_dst);
    asm volatile("cp.async.cg.shared.global [%0], [%1], 16;"
                 :: "r"(s), "l"(gmem_src));
}
#define CP_COMMIT()      asm volatile("cp.async.commit_group;")
#define CP_WAIT(n)       asm volatile("cp.async.wait_group %0;" :: "n"(n))

__device__ __forceinline__ float fast_sigmoid(float x) {
    float t;
    asm("tanh.approx.f32 %0, %1;" : "=f"(t) : "f"(x * 0.5f));
    return fmaf(t, 0.5f, 0.5f);
}

__device__ __forceinline__ void stg_cs_f2(float* p, float a, float b) {
    asm volatile("st.global.cs.v2.f32 [%0], {%1,%2};"
                 :: "l"(p), "f"(a), "f"(b) : "memory");
}
__device__ __forceinline__ void stg_cs_f1(float* p, float a) {
    asm volatile("st.global.cs.f32 [%0], %1;" :: "l"(p), "f"(a) : "memory");
}

// ---------------------------------------------------------------------------
// Layer-1 GEMM on tensor cores (unchanged; BM=64, BN=128 measured best)
// ---------------------------------------------------------------------------
#define LDA 36

template<int BM, int BN, bool RELU>
__global__ __launch_bounds__(256)
void gemm_mma_kernel(const float* __restrict__ A,
                     const float* __restrict__ W,
                     const float* __restrict__ bias,
                     float* __restrict__ C,
                     int K, int Nn)
{
    constexpr int LDW = BN + 4;
    constexpr int WN  = BN / 32;
    constexpr int WM  = 8 / WN;
    constexpr int MT  = BM / (WM * 16);
    constexpr int NT  = 4;
    static_assert(MT >= 1, "bad BM/BN combo");

    constexpr int A_FLOATS = BM * LDA;
    constexpr int W_FLOATS = 32 * LDW;

    __shared__ float smem[2 * (A_FLOATS + W_FLOATS)];
    float* Asb[2] = { smem, smem + A_FLOATS + W_FLOATS };
    float* Wsb[2] = { smem + A_FLOATS, smem + 2*A_FLOATS + W_FLOATS };

    const int tid  = threadIdx.x;
    const int lane = tid & 31;
    const int wid  = tid >> 5;
    const int wm   = (wid / WN) * (MT * 16);
    const int wn   = (wid % WN) * 32;
    const int qr   = lane >> 2;
    const int qc   = lane & 3;
    const int rowBase = blockIdx.y * BM;
    const int colBase = blockIdx.x * BN;

    auto load_tiles = [&](int kk, int buf) {
        float* As = Asb[buf];
        float* Ws = Wsb[buf];
#pragma unroll
        for (int v = tid; v < BM * 8; v += 256) {
            const int r  = v >> 3;
            const int c4 = (v & 7) * 4;
            cp_async16(&As[r * LDA + c4],
                       &A[(size_t)(rowBase + r) * K + kk + c4]);
        }
#pragma unroll
        for (int v = tid; v < 32 * (BN/4); v += 256) {
            const int kr = v / (BN/4);
            const int n4 = (v % (BN/4)) * 4;
            cp_async16(&Ws[kr * LDW + n4],
                       &W[(size_t)(kk + kr) * Nn + colBase + n4]);
        }
        CP_COMMIT();
    };

    float acc[MT][NT][4];
#pragma unroll
    for (int mt = 0; mt < MT; mt++)
#pragma unroll
        for (int nt = 0; nt < NT; nt++)
#pragma unroll
            for (int i = 0; i < 4; i++) acc[mt][nt][i] = 0.f;

    load_tiles(0, 0);

    int buf = 0;
    for (int kk = 0; kk < K; kk += 32, buf ^= 1) {
        if (kk + 32 < K) {
            load_tiles(kk + 32, buf ^ 1);
            CP_WAIT(1);
        } else {
            CP_WAIT(0);
        }
        __syncthreads();

        const float* As = Asb[buf];
        const float* Ws = Wsb[buf];
#pragma unroll
        for (int k0 = 0; k0 < 32; k0 += 8) {
            uint32_t a[MT][4], b[NT][2];
#pragma unroll
            for (int mt = 0; mt < MT; mt++) {
                const float* base = &As[(wm + mt*16 + qr) * LDA + k0 + qc];
                a[mt][0] = f32_to_tf32(base[0]);
                a[mt][1] = f32_to_tf32(base[8 * LDA]);
                a[mt][2] = f32_to_tf32(base[4]);
                a[mt][3] = f32_to_tf32(base[8 * LDA + 4]);
            }
#pragma unroll
            for (int nt = 0; nt < NT; nt++) {
                const float* base = &Ws[(k0 + qc) * LDW + wn + nt*8 + qr];
                b[nt][0] = f32_to_tf32(base[0]);
                b[nt][1] = f32_to_tf32(base[4 * LDW]);
            }
#pragma unroll
            for (int mt = 0; mt < MT; mt++)
#pragma unroll
                for (int nt = 0; nt < NT; nt++)
                    mma_tf32(acc[mt][nt], a[mt], b[nt]);
        }
        __syncthreads();
    }

#pragma unroll
    for (int mt = 0; mt < MT; mt++) {
#pragma unroll
        for (int nt = 0; nt < NT; nt++) {
            float* d = acc[mt][nt];
            const int c = colBase + wn + nt*8 + qc*2;
            float bx = bias[c], by = bias[c+1];
            float2 lo = make_float2(d[0] + bx, d[1] + by);
            float2 hi = make_float2(d[2] + bx, d[3] + by);
            if (RELU) {
                lo.x = fmaxf(lo.x, 0.f); lo.y = fmaxf(lo.y, 0.f);
                hi.x = fmaxf(hi.x, 0.f); hi.y = fmaxf(hi.y, 0.f);
            }
            const size_t r0 = rowBase + wm + mt*16 + qr;
            *reinterpret_cast<float2*>(&C[r0 * Nn + c])     = lo;
            *reinterpret_cast<float2*>(&C[(r0+8) * Nn + c]) = hi;
        }
    }
}

// ---------------------------------------------------------------------------
// Fused layers 2+3: zn = normalize(relu(h0 @ W1 + b1) @ W2 + b2)
// One block = 64 rows. Phase 1: 64x256 GEMM (acc in regs, h1 staged to smem).
// Phase 2: 64x64 GEMM reading A directly from smem. Fused bias+row-normalize.
// Smem (floats): [0,2304) A1b0 | [2304,4608) A1b1 | [4608,12928) W1b0 |
// [12928,21248) W1b1 ; after phase 1: h1s = [0,16640) (64x260),
// W2 bufs = [16640,18816),[18816,20992) ; norm stage reuses [16640,+4352).
// ---------------------------------------------------------------------------
#define F23_SMEM_FLOATS 21248
#define F23_SMEM_BYTES  (F23_SMEM_FLOATS * 4)   // 84,992 B

__global__ __launch_bounds__(256)
void fused_l23_kernel(const float* __restrict__ h0,
                      const float* __restrict__ W1,
                      const float* __restrict__ b1,
                      const float* __restrict__ W2,
                      const float* __restrict__ b2,
                      float* __restrict__ zn)
{
    extern __shared__ float smem[];
    float* A1b[2] = { smem,         smem + 2304 };
    float* W1b[2] = { smem + 4608,  smem + 12928 };
    float* h1s    = smem;                       // 64 x 260 (aliases A1/W1)
    float* W2b[2] = { smem + 16640, smem + 18816 };
    float* nstage = smem + 16640;               // 64 x 68  (aliases W2 bufs)

    const int tid  = threadIdx.x;
    const int lane = tid & 31;
    const int wid  = tid >> 5;
    const int qr   = lane >> 2;
    const int qc   = lane & 3;
    const int rowBase = blockIdx.x * 64;

    // ================= phase 1: h1 = relu(h0 @ W1 + b1)  (64x256) =========
    const int wn1 = wid * 32;                   // 8 warps across N=256

    auto load1 = [&](int kk, int buf) {
#pragma unroll
        for (int v = tid; v < 512; v += 256) {  // A: 64x32
            const int r  = v >> 3;
            const int c4 = (v & 7) * 4;
            cp_async16(&A1b[buf][r * 36 + c4],
                       &h0[(size_t)(rowBase + r) * HID + kk + c4]);
        }
#pragma unroll
        for (int v = tid; v < 2048; v += 256) { // W1: 32x256
            const int kr = v >> 6;
            const int n4 = (v & 63) * 4;
            cp_async16(&W1b[buf][kr * 260 + n4],
                       &W1[(size_t)(kk + kr) * HID + n4]);
        }
        CP_COMMIT();
    };

    float acc1[4][4][4];
#pragma unroll
    for (int mt = 0; mt < 4; mt++)
#pragma unroll
        for (int nt = 0; nt < 4; nt++)
#pragma unroll
            for (int i = 0; i < 4; i++) acc1[mt][nt][i] = 0.f;

    load1(0, 0);
    int buf = 0;
    for (int kk = 0; kk < HID; kk += 32, buf ^= 1) {
        if (kk + 32 < HID) {
            load1(kk + 32, buf ^ 1);
            CP_WAIT(1);
        } else {
            CP_WAIT(0);
        }
        __syncthreads();
#pragma unroll
        for (int k0 = 0; k0 < 32; k0 += 8) {
            uint32_t a[4][4], b[4][2];
#pragma unroll
            for (int mt = 0; mt < 4; mt++) {
                const float* base = &A1b[buf][(mt*16 + qr) * 36 + k0 + qc];
                a[mt][0] = f32_to_tf32(base[0]);
                a[mt][1] = f32_to_tf32(base[8 * 36]);
                a[mt][2] = f32_to_tf32(base[4]);
                a[mt][3] = f32_to_tf32(base[8 * 36 + 4]);
            }
#pragma unroll
            for (int nt = 0; nt < 4; nt++) {
                const float* base = &W1b[buf][(k0 + qc) * 260 + wn1 + nt*8 + qr];
                b[nt][0] = f32_to_tf32(base[0]);
                b[nt][1] = f32_to_tf32(base[4 * 260]);
            }
#pragma unroll
            for (int mt = 0; mt < 4; mt++)
#pragma unroll
                for (int nt = 0; nt < 4; nt++)
                    mma_tf32(acc1[mt][nt], a[mt], b[nt]);
        }
        __syncthreads();
    }

    // prefetch W2 k=0 (region disjoint from h1s), then stage h1 into smem
#pragma unroll
    for (int v = tid; v < 512; v += 256) {      // W2: 32x64
        const int kr = v >> 4;
        const int n4 = (v & 15) * 4;
        cp_async16(&W2b[0][kr * 68 + n4], &W2[(size_t)kr * D_OUT + n4]);
    }
    CP_COMMIT();

#pragma unroll
    for (int mt = 0; mt < 4; mt++) {
#pragma unroll
        for (int nt = 0; nt < 4; nt++) {
            float* d = acc1[mt][nt];
            const int c = wn1 + nt*8 + qc*2;
            const float bx = b1[c], by = b1[c+1];
            const int r = mt*16 + qr;
            *reinterpret_cast<float2*>(&h1s[r * 260 + c]) =
                make_float2(fmaxf(d[0] + bx, 0.f), fmaxf(d[1] + by, 0.f));
            *reinterpret_cast<float2*>(&h1s[(r+8) * 260 + c]) =
                make_float2(fmaxf(d[2] + bx, 0.f), fmaxf(d[3] + by, 0.f));
        }
    }
    __syncthreads();

    // ================= phase 2: z = h1s @ W2 + b2  (64x64) =================
    const int wn3 = (wid & 1) * 32;
    const int wm3 = (wid >> 1) * 16;

    float acc3[4][4];
#pragma unroll
    for (int nt = 0; nt < 4; nt++)
#pragma unroll
        for (int i = 0; i < 4; i++) acc3[nt][i] = 0.f;

    buf = 0;
    for (int kk = 0; kk < HID; kk += 32, buf ^= 1) {
        if (kk + 32 < HID) {
#pragma unroll
            for (int v = tid; v < 512; v += 256) {
                const int kr = v >> 4;
                const int n4 = (v & 15) * 4;
                cp_async16(&W2b[buf ^ 1][kr * 68 + n4],
                           &W2[(size_t)(kk + 32 + kr) * D_OUT + n4]);
            }
            CP_COMMIT();
            CP_WAIT(1);
        } else {
            CP_WAIT(0);
        }
        __syncthreads();
#pragma unroll
        for (int k0 = 0; k0 < 32; k0 += 8) {
            uint32_t a[4], b[4][2];
            {
                const float* base = &h1s[(wm3 + qr) * 260 + kk + k0 + qc];
                a[0] = f32_to_tf32(base[0]);
                a[1] = f32_to_tf32(base[8 * 260]);
                a[2] = f32_to_tf32(base[4]);
                a[3] = f32_to_tf32(base[8 * 260 + 4]);
            }
#pragma unroll
            for (int nt = 0; nt < 4; nt++) {
                const float* base = &W2b[buf][(k0 + qc) * 68 + wn3 + nt*8 + qr];
                b[nt][0] = f32_to_tf32(base[0]);
                b[nt][1] = f32_to_tf32(base[4 * 68]);
            }
#pragma unroll
            for (int nt = 0; nt < 4; nt++)
                mma_tf32(acc3[nt], a, b[nt]);
        }
        __syncthreads();
    }

    // epilogue: bias + stage + row-normalize -> zn
#pragma unroll
    for (int nt = 0; nt < 4; nt++) {
        float* d = acc3[nt];
        const int c = wn3 + nt*8 + qc*2;
        const float bx = b2[c], by = b2[c+1];
        const int r = wm3 + qr;
        *reinterpret_cast<float2*>(&nstage[r * 68 + c]) =
            make_float2(d[0] + bx, d[1] + by);
        *reinterpret_cast<float2*>(&nstage[(r+8) * 68 + c]) =
            make_float2(d[2] + bx, d[3] + by);
    }
    __syncthreads();
#pragma unroll
    for (int rr = 0; rr < 8; rr++) {
        const int r = wid * 8 + rr;
        float2 v = *reinterpret_cast<const float2*>(&nstage[r * 68 + lane*2]);
        float ss = v.x*v.x + v.y*v.y;
#pragma unroll
        for (int o = 16; o > 0; o >>= 1)
            ss += __shfl_xor_sync(0xffffffffu, ss, o);
        float inv = rsqrtf(fmaxf(ss, 1e-30f));
        *reinterpret_cast<float2*>(&zn[(size_t)(rowBase + r) * D_OUT + lane*2]) =
            make_float2(v.x * inv, v.y * inv);
    }
}

// ---------------------------------------------------------------------------
// Edge reconstruction loss (edge_index is int32) — separate kernel (proven)
// ---------------------------------------------------------------------------
__global__ __launch_bounds__(256)
void edge_loss_kernel(const int* __restrict__ ei,
                      const float* __restrict__ Zn)
{
    const int lane = threadIdx.x & 31;
    const int warp = threadIdx.x >> 5;
    const int gw   = blockIdx.x * 8 + warp;
    const int nw   = gridDim.x * 8;
    float lsum = 0.f;
    for (int e = gw; e < E_EDGES; e += nw) {
        const int s = ei[e];
        const int d = ei[E_EDGES + e];
        float2 a = *reinterpret_cast<const float2*>(&Zn[(size_t)s * D_OUT + lane*2]);
        float2 b = *reinterpret_cast<const float2*>(&Zn[(size_t)d * D_OUT + lane*2]);
        float p = a.x*b.x + a.y*b.y;
#pragma unroll
        for (int o = 16; o > 0; o >>= 1) p += __shfl_xor_sync(0xffffffffu, p, o);
        if (lane == 0) lsum += log1pf(__expf(-p));
    }
    __shared__ float wsum[8];
    if (lane == 0) wsum[warp] = lsum;
    __syncthreads();
    if (threadIdx.x == 0) {
        float t = 0.f;
#pragma unroll
        for (int i = 0; i < 8; i++) t += wsum[i];
        atomicAdd(&g_loss_sum, (double)t);
    }
}

__global__ void zero_loss_kernel() { g_loss_sum = 0.0; }

__global__ void write_loss_kernel(float* __restrict__ out)
{
    out[(size_t)N_NODES * N_NODES] = (float)(g_loss_sum / (double)E_EDGES);
}

// ---------------------------------------------------------------------------
// Gram + sigmoid via tf32 mma (exact R14 measured-best structure)
// ---------------------------------------------------------------------------
#define GRAM_LDK  68
#define GRAM_LDS  132
#define GRAM_SMEM_BYTES (2 * 128 * GRAM_LDK * 4)   // 69,632 B

__global__ __launch_bounds__(256)
void gram_mma_kernel(const float* __restrict__ Z, float* __restrict__ Out)
{
    extern __shared__ float smem[];
    float* As = smem;
    float* Bs = smem + 128 * GRAM_LDK;

    const int bi = blockIdx.y;
    const int bj = blockIdx.x;
    if (bj < bi) return;
    const int rowBase = bi * 128;
    const int colBase = bj * 128;

    const int tid  = threadIdx.x;
    const int lane = tid & 31;
    const int wid  = tid >> 5;
    const int wm   = (wid >> 2) * 64;
    const int wn   = (wid & 3) * 32;
    const int qr   = lane >> 2;
    const int qc   = lane & 3;

    for (int v = tid; v < 128 * 16; v += 256) {
        const int r  = v >> 4;
        const int c4 = (v & 15) * 4;
        cp_async16(&As[r * GRAM_LDK + c4],
                   &Z[(size_t)(rowBase + r) * D_OUT + c4]);
    }
    if (bj != bi) {
        for (int v = tid; v < 128 * 16; v += 256) {
            const int r  = v >> 4;
            const int c4 = (v & 15) * 4;
            cp_async16(&Bs[r * GRAM_LDK + c4],
                       &Z[(size_t)(colBase + r) * D_OUT + c4]);
        }
    }
    CP_COMMIT();
    CP_WAIT(0);
    __syncthreads();

    const float* Bp = (bj == bi) ? As : Bs;

    float acc[4][4][4];
#pragma unroll
    for (int mt = 0; mt < 4; mt++)
#pragma unroll
        for (int nt = 0; nt < 4; nt++)
#pragma unroll
            for (int i = 0; i < 4; i++) acc[mt][nt][i] = 0.f;

#pragma unroll
    for (int k0 = 0; k0 < D_OUT; k0 += 8) {
        uint32_t a[4][4], b[4][2];
#pragma unroll
        for (int mt = 0; mt < 4; mt++) {
            const float* base = &As[(wm + mt*16 + qr) * GRAM_LDK + k0 + qc];
            a[mt][0] = f32_to_tf32(base[0]);
            a[mt][1] = f32_to_tf32(base[8 * GRAM_LDK]);
            a[mt][2] = f32_to_tf32(base[4]);
            a[mt][3] = f32_to_tf32(base[8 * GRAM_LDK + 4]);
        }
#pragma unroll
        for (int nt = 0; nt < 4; nt++) {
            const float* base = &Bp[(wn + nt*8 + qr) * GRAM_LDK + k0 + qc];
            b[nt][0] = f32_to_tf32(base[0]);
            b[nt][1] = f32_to_tf32(base[4]);
        }
#pragma unroll
        for (int mt = 0; mt < 4; mt++)
#pragma unroll
            for (int nt = 0; nt < 4; nt++)
                mma_tf32(acc[mt][nt], a[mt], b[nt]);
    }

#pragma unroll
    for (int mt = 0; mt < 4; mt++) {
#pragma unroll
        for (int nt = 0; nt < 4; nt++) {
            float* d = acc[mt][nt];
            d[0] = fast_sigmoid(d[0]);
            d[1] = fast_sigmoid(d[1]);
            d[2] = fast_sigmoid(d[2]);
            d[3] = fast_sigmoid(d[3]);
            const size_t r = rowBase + wm + mt*16 + qr;
            const int    c = colBase + wn + nt*8 + qc*2;
            stg_cs_f2(&Out[r * N_NODES + c],     d[0], d[1]);
            stg_cs_f2(&Out[(r+8) * N_NODES + c], d[2], d[3]);
        }
    }

    if (bj > bi) {
        __syncthreads();
        float* stg = smem;
#pragma unroll
        for (int mt = 0; mt < 4; mt++) {
#pragma unroll
            for (int nt = 0; nt < 4; nt++) {
                float* d = acc[mt][nt];
                const int r = wm + mt*16 + qr;
                const int c = wn + nt*8 + qc*2;
                *reinterpret_cast<float2*>(&stg[r * GRAM_LDS + c]) =
                    make_float2(d[0], d[1]);
                *reinterpret_cast<float2*>(&stg[(r+8) * GRAM_LDS + c]) =
                    make_float2(d[2], d[3]);
            }
        }
        __syncthreads();
        for (int v = tid; v < 128 * 32; v += 256) {
            const int cc = v & 127;
            const int r2 = (v >> 7) * 4;
            float4 t = *reinterpret_cast<const float4*>(&stg[cc * GRAM_LDS + r2]);
            float* ob = &Out[(size_t)(colBase + r2) * N_NODES + rowBase + cc];
            stg_cs_f1(ob,             t.x);
            stg_cs_f1(ob + N_NODES,   t.y);
            stg_cs_f1(ob + 2*N_NODES, t.z);
            stg_cs_f1(ob + 3*N_NODES, t.w);
        }
    }
}

// ---------------------------------------------------------------------------
extern "C" void kernel_launch(void* const* d_in, const int* in_sizes, int n_in,
                              void* d_out, int out_size)
{
    const float* x  = (const float*)d_in[0];
    const int*   ei = (const int*)  d_in[1];
    const float* W0 = (const float*)d_in[2];
    const float* b0 = (const float*)d_in[3];
    const float* W1 = (const float*)d_in[4];
    const float* b1 = (const float*)d_in[5];
    const float* W2 = (const float*)d_in[6];
    const float* b2 = (const float*)d_in[7];
    float* out = (float*)d_out;

    void *p_h0, *p_zn;
    cudaGetSymbolAddress(&p_h0, g_h0);
    cudaGetSymbolAddress(&p_zn, g_zn);
    float* h0 = (float*)p_h0;
    float* zn = (float*)p_zn;

    cudaFuncSetAttribute(gram_mma_kernel,
                         cudaFuncAttributeMaxDynamicSharedMemorySize,
                         GRAM_SMEM_BYTES);
    cudaFuncSetAttribute(fused_l23_kernel,
                         cudaFuncAttributeMaxDynamicSharedMemorySize,
                         F23_SMEM_BYTES);

    zero_loss_kernel<<<1, 1>>>();

    // layer 1 (unchanged best config)
    gemm_mma_kernel<64, 128, true><<<dim3(HID/128, N_NODES/64), 256>>>(
        x, W0, b0, h0, D_IN, HID);

    // fused layers 2+3 (h1 never touches HBM) + row-normalize -> zn
    fused_l23_kernel<<<N_NODES/64, 256, F23_SMEM_BYTES>>>(
        h0, W1, b1, W2, b2, zn);

    // edge loss (separate, proven config)
    edge_loss_kernel<<<1024, 256>>>(ei, zn);

    // full similarity matrix (symmetric, tensor-core, 2D grid + early exit)
    gram_mma_kernel<<<dim3(N_NODES/128, N_NODES/128), 256, GRAM_SMEM_BYTES>>>(zn, out);

    // scalar loss at the end of the output buffer
    if ((long long)out_size > (long long)N_NODES * N_NODES)
        write_loss_kernel<<<1, 1>>>(out);
}

// round 16
// speedup vs baseline: 1.0928x; 1.0928x over previous
#include <cuda_runtime.h>
#include <math.h>
#include <stdint.h>

#define N_NODES 12288
#define D_IN    512
#define HID     256
#define D_OUT   64
#define E_EDGES 393216

// ---------------- scratch (device globals: no runtime allocation) ----------
__device__ float  g_h0[(size_t)N_NODES * HID];
__device__ float  g_h1[(size_t)N_NODES * HID];
__device__ float  g_zn[(size_t)N_NODES * D_OUT];
__device__ double g_loss_sum;

// ---------------------------------------------------------------------------
// tf32 / cp.async / sigmoid / streaming-store helpers
// ---------------------------------------------------------------------------
__device__ __forceinline__ uint32_t f32_to_tf32(float x) {
    uint32_t r;
    asm("cvt.rna.tf32.f32 %0, %1;" : "=r"(r) : "f"(x));
    return r;
}

__device__ __forceinline__ void mma_tf32(float d[4],
                                         const uint32_t a[4],
                                         const uint32_t b[2]) {
    asm volatile(
        "mma.sync.aligned.m16n8k8.row.col.f32.tf32.tf32.f32 "
        "{%0,%1,%2,%3}, {%4,%5,%6,%7}, {%8,%9}, {%0,%1,%2,%3};"
        : "+f"(d[0]), "+f"(d[1]), "+f"(d[2]), "+f"(d[3])
        : "r"(a[0]), "r"(a[1]), "r"(a[2]), "r"(a[3]),
          "r"(b[0]), "r"(b[1]));
}

__device__ __forceinline__ void cp_async16(float* smem_dst, const float* gmem_src) {
    uint32_t s = (uint32_t)__cvta_generic_to_shared(smem_dst);
    asm volatile("cp.async.cg.shared.global [%0], [%1], 16;"
                 :: "r"(s), "l"(gmem_src));
}
#define CP_COMMIT()      asm volatile("cp.async.commit_group;")
#define CP_WAIT(n)       asm volatile("cp.async.wait_group %0;" :: "n"(n))

__device__ __forceinline__ float fast_sigmoid(float x) {
    float t;
    asm("tanh.approx.f32 %0, %1;" : "=f"(t) : "f"(x * 0.5f));
    return fmaf(t, 0.5f, 0.5f);
}

__device__ __forceinline__ void stg_cs_f2(float* p, float a, float b) {
    asm volatile("st.global.cs.v2.f32 [%0], {%1,%2};"
                 :: "l"(p), "f"(a), "f"(b) : "memory");
}
__device__ __forceinline__ void stg_cs_f1(float* p, float a) {
    asm volatile("st.global.cs.f32 [%0], %1;" :: "l"(p), "f"(a) : "memory");
}

// ---------------------------------------------------------------------------
// Encoder GEMM on tensor cores, cp.async double-buffered (exact R14 config).
//   Layers 1,2: BM=64,  BN=128
//   Layer  3 : BM=128, BN=64  (fused row-normalize)
// ---------------------------------------------------------------------------
#define LDA 36

template<int BM, int BN, bool RELU, bool NORM>
__global__ __launch_bounds__(256)
void gemm_mma_kernel(const float* __restrict__ A,
                     const float* __restrict__ W,
                     const float* __restrict__ bias,
                     float* __restrict__ C,
                     int K, int Nn)
{
    constexpr int LDW = BN + 4;
    constexpr int WN  = BN / 32;
    constexpr int WM  = 8 / WN;
    constexpr int MT  = BM / (WM * 16);
    constexpr int NT  = 4;
    static_assert(MT >= 1, "bad BM/BN combo");

    constexpr int A_FLOATS = BM * LDA;
    constexpr int W_FLOATS = 32 * LDW;
    constexpr int NEED_MAIN = 2 * (A_FLOATS + W_FLOATS);
    constexpr int NEED_STG  = NORM ? BM * 68 : 0;
    constexpr int SMEM_FLOATS = NEED_MAIN > NEED_STG ? NEED_MAIN : NEED_STG;

    __shared__ float smem[SMEM_FLOATS];
    float* Asb[2] = { smem, smem + A_FLOATS + W_FLOATS };
    float* Wsb[2] = { smem + A_FLOATS, smem + 2*A_FLOATS + W_FLOATS };

    const int tid  = threadIdx.x;
    const int lane = tid & 31;
    const int wid  = tid >> 5;
    const int wm   = (wid / WN) * (MT * 16);
    const int wn   = (wid % WN) * 32;
    const int qr   = lane >> 2;
    const int qc   = lane & 3;
    const int rowBase = blockIdx.y * BM;
    const int colBase = blockIdx.x * BN;

    auto load_tiles = [&](int kk, int buf) {
        float* As = Asb[buf];
        float* Ws = Wsb[buf];
#pragma unroll
        for (int v = tid; v < BM * 8; v += 256) {
            const int r  = v >> 3;
            const int c4 = (v & 7) * 4;
            cp_async16(&As[r * LDA + c4],
                       &A[(size_t)(rowBase + r) * K + kk + c4]);
        }
#pragma unroll
        for (int v = tid; v < 32 * (BN/4); v += 256) {
            const int kr = v / (BN/4);
            const int n4 = (v % (BN/4)) * 4;
            cp_async16(&Ws[kr * LDW + n4],
                       &W[(size_t)(kk + kr) * Nn + colBase + n4]);
        }
        CP_COMMIT();
    };

    float acc[MT][NT][4];
#pragma unroll
    for (int mt = 0; mt < MT; mt++)
#pragma unroll
        for (int nt = 0; nt < NT; nt++)
#pragma unroll
            for (int i = 0; i < 4; i++) acc[mt][nt][i] = 0.f;

    load_tiles(0, 0);

    int buf = 0;
    for (int kk = 0; kk < K; kk += 32, buf ^= 1) {
        if (kk + 32 < K) {
            load_tiles(kk + 32, buf ^ 1);
            CP_WAIT(1);
        } else {
            CP_WAIT(0);
        }
        __syncthreads();

        const float* As = Asb[buf];
        const float* Ws = Wsb[buf];
#pragma unroll
        for (int k0 = 0; k0 < 32; k0 += 8) {
            uint32_t a[MT][4], b[NT][2];
#pragma unroll
            for (int mt = 0; mt < MT; mt++) {
                const float* base = &As[(wm + mt*16 + qr) * LDA + k0 + qc];
                a[mt][0] = f32_to_tf32(base[0]);
                a[mt][1] = f32_to_tf32(base[8 * LDA]);
                a[mt][2] = f32_to_tf32(base[4]);
                a[mt][3] = f32_to_tf32(base[8 * LDA + 4]);
            }
#pragma unroll
            for (int nt = 0; nt < NT; nt++) {
                const float* base = &Ws[(k0 + qc) * LDW + wn + nt*8 + qr];
                b[nt][0] = f32_to_tf32(base[0]);
                b[nt][1] = f32_to_tf32(base[4 * LDW]);
            }
#pragma unroll
            for (int mt = 0; mt < MT; mt++)
#pragma unroll
                for (int nt = 0; nt < NT; nt++)
                    mma_tf32(acc[mt][nt], a[mt], b[nt]);
        }
        __syncthreads();
    }

    if (!NORM) {
#pragma unroll
        for (int mt = 0; mt < MT; mt++) {
#pragma unroll
            for (int nt = 0; nt < NT; nt++) {
                float* d = acc[mt][nt];
                const int c = colBase + wn + nt*8 + qc*2;
                float bx = bias[c], by = bias[c+1];
                float2 lo = make_float2(d[0] + bx, d[1] + by);
                float2 hi = make_float2(d[2] + bx, d[3] + by);
                if (RELU) {
                    lo.x = fmaxf(lo.x, 0.f); lo.y = fmaxf(lo.y, 0.f);
                    hi.x = fmaxf(hi.x, 0.f); hi.y = fmaxf(hi.y, 0.f);
                }
                const size_t r0 = rowBase + wm + mt*16 + qr;
                *reinterpret_cast<float2*>(&C[r0 * Nn + c])     = lo;
                *reinterpret_cast<float2*>(&C[(r0+8) * Nn + c]) = hi;
            }
        }
    } else {
        constexpr int LDS = 68;
        float* stg = smem;
        __syncthreads();
#pragma unroll
        for (int mt = 0; mt < MT; mt++) {
#pragma unroll
            for (int nt = 0; nt < NT; nt++) {
                float* d = acc[mt][nt];
                const int c = wn + nt*8 + qc*2;
                float bx = bias[c], by = bias[c+1];
                const int r = wm + mt*16 + qr;
                *reinterpret_cast<float2*>(&stg[r * LDS + c]) =
                    make_float2(d[0] + bx, d[1] + by);
                *reinterpret_cast<float2*>(&stg[(r+8) * LDS + c]) =
                    make_float2(d[2] + bx, d[3] + by);
            }
        }
        __syncthreads();
#pragma unroll
        for (int rr = 0; rr < BM/8; rr++) {
            const int r = wid * (BM/8) + rr;
            float2 v = *reinterpret_cast<const float2*>(&stg[r * LDS + lane*2]);
            float ss = v.x*v.x + v.y*v.y;
#pragma unroll
            for (int o = 16; o > 0; o >>= 1)
                ss += __shfl_xor_sync(0xffffffffu, ss, o);
            float inv = rsqrtf(fmaxf(ss, 1e-30f));
            *reinterpret_cast<float2*>(&C[(size_t)(rowBase + r) * D_OUT + lane*2]) =
                make_float2(v.x * inv, v.y * inv);
        }
    }
}

// ---------------------------------------------------------------------------
// Edge reconstruction loss, restructured: 4 edges per warp, 8 lanes/edge.
// Per lane: 8 floats from each endpoint row (2x float4), 8 FMAs; 3-shfl
// reduction shared across 4 edges; log1p in 4 parallel lanes. Final 5-shfl
// warp sum happens ONCE at the end, not per edge.
// ---------------------------------------------------------------------------
__global__ __launch_bounds__(256)
void edge_loss_kernel(const int* __restrict__ ei,
                      const float* __restrict__ Zn)
{
    const int lane = threadIdx.x & 31;
    const int wid  = threadIdx.x >> 5;
    const int g    = lane >> 3;          // edge slot within warp: 0..3
    const int l    = lane & 7;           // lane within edge group
    const int gw   = blockIdx.x * 8 + wid;     // global warp id
    const int nw   = gridDim.x * 8;            // total warps

    float lsum = 0.f;
    for (int e0 = gw * 4; e0 < E_EDGES; e0 += nw * 4) {
        const int e = e0 + g;                  // E_EDGES % 4 == 0, always valid
        const int s = ei[e];
        const int d = ei[E_EDGES + e];
        const float4* sp = reinterpret_cast<const float4*>(&Zn[(size_t)s * D_OUT + l*8]);
        const float4* dp = reinterpret_cast<const float4*>(&Zn[(size_t)d * D_OUT + l*8]);
        float4 a0 = sp[0], a1 = sp[1];
        float4 b0 = dp[0], b1 = dp[1];
        float p = a0.x*b0.x + a0.y*b0.y + a0.z*b0.z + a0.w*b0.w
                + a1.x*b1.x + a1.y*b1.y + a1.z*b1.z + a1.w*b1.w;
        // reduce within the 8-lane group (xor offsets < 8 stay in-group)
        p += __shfl_xor_sync(0xffffffffu, p, 4);
        p += __shfl_xor_sync(0xffffffffu, p, 2);
        p += __shfl_xor_sync(0xffffffffu, p, 1);
        if (l == 0) lsum += log1pf(__expf(-p));   // 4 lanes/warp in parallel
    }

    // one warp-wide sum at the end (covers lanes 0,8,16,24; others are 0)
#pragma unroll
    for (int o = 16; o > 0; o >>= 1)
        lsum += __shfl_xor_sync(0xffffffffu, lsum, o);

    __shared__ float wsum[8];
    if (lane == 0) wsum[wid] = lsum;
    __syncthreads();
    if (threadIdx.x == 0) {
        float t = 0.f;
#pragma unroll
        for (int i = 0; i < 8; i++) t += wsum[i];
        atomicAdd(&g_loss_sum, (double)t);
    }
}

__global__ void zero_loss_kernel() { g_loss_sum = 0.0; }

__global__ void write_loss_kernel(float* __restrict__ out)
{
    out[(size_t)N_NODES * N_NODES] = (float)(g_loss_sum / (double)E_EDGES);
}

// ---------------------------------------------------------------------------
// Gram + sigmoid via tf32 mma (exact R14 measured-best structure)
// ---------------------------------------------------------------------------
#define GRAM_LDK  68
#define GRAM_LDS  132
#define GRAM_SMEM_BYTES (2 * 128 * GRAM_LDK * 4)   // 69,632 B

__global__ __launch_bounds__(256)
void gram_mma_kernel(const float* __restrict__ Z, float* __restrict__ Out)
{
    extern __shared__ float smem[];
    float* As = smem;
    float* Bs = smem + 128 * GRAM_LDK;

    const int bi = blockIdx.y;
    const int bj = blockIdx.x;
    if (bj < bi) return;
    const int rowBase = bi * 128;
    const int colBase = bj * 128;

    const int tid  = threadIdx.x;
    const int lane = tid & 31;
    const int wid  = tid >> 5;
    const int wm   = (wid >> 2) * 64;
    const int wn   = (wid & 3) * 32;
    const int qr   = lane >> 2;
    const int qc   = lane & 3;

    for (int v = tid; v < 128 * 16; v += 256) {
        const int r  = v >> 4;
        const int c4 = (v & 15) * 4;
        cp_async16(&As[r * GRAM_LDK + c4],
                   &Z[(size_t)(rowBase + r) * D_OUT + c4]);
    }
    if (bj != bi) {
        for (int v = tid; v < 128 * 16; v += 256) {
            const int r  = v >> 4;
            const int c4 = (v & 15) * 4;
            cp_async16(&Bs[r * GRAM_LDK + c4],
                       &Z[(size_t)(colBase + r) * D_OUT + c4]);
        }
    }
    CP_COMMIT();
    CP_WAIT(0);
    __syncthreads();

    const float* Bp = (bj == bi) ? As : Bs;

    float acc[4][4][4];
#pragma unroll
    for (int mt = 0; mt < 4; mt++)
#pragma unroll
        for (int nt = 0; nt < 4; nt++)
#pragma unroll
            for (int i = 0; i < 4; i++) acc[mt][nt][i] = 0.f;

#pragma unroll
    for (int k0 = 0; k0 < D_OUT; k0 += 8) {
        uint32_t a[4][4], b[4][2];
#pragma unroll
        for (int mt = 0; mt < 4; mt++) {
            const float* base = &As[(wm + mt*16 + qr) * GRAM_LDK + k0 + qc];
            a[mt][0] = f32_to_tf32(base[0]);
            a[mt][1] = f32_to_tf32(base[8 * GRAM_LDK]);
            a[mt][2] = f32_to_tf32(base[4]);
            a[mt][3] = f32_to_tf32(base[8 * GRAM_LDK + 4]);
        }
#pragma unroll
        for (int nt = 0; nt < 4; nt++) {
            const float* base = &Bp[(wn + nt*8 + qr) * GRAM_LDK + k0 + qc];
            b[nt][0] = f32_to_tf32(base[0]);
            b[nt][1] = f32_to_tf32(base[4]);
        }
#pragma unroll
        for (int mt = 0; mt < 4; mt++)
#pragma unroll
            for (int nt = 0; nt < 4; nt++)
                mma_tf32(acc[mt][nt], a[mt], b[nt]);
    }

#pragma unroll
    for (int mt = 0; mt < 4; mt++) {
#pragma unroll
        for (int nt = 0; nt < 4; nt++) {
            float* d = acc[mt][nt];
            d[0] = fast_sigmoid(d[0]);
            d[1] = fast_sigmoid(d[1]);
            d[2] = fast_sigmoid(d[2]);
            d[3] = fast_sigmoid(d[3]);
            const size_t r = rowBase + wm + mt*16 + qr;
            const int    c = colBase + wn + nt*8 + qc*2;
            stg_cs_f2(&Out[r * N_NODES + c],     d[0], d[1]);
            stg_cs_f2(&Out[(r+8) * N_NODES + c], d[2], d[3]);
        }
    }

    if (bj > bi) {
        __syncthreads();
        float* stg = smem;
#pragma unroll
        for (int mt = 0; mt < 4; mt++) {
#pragma unroll
            for (int nt = 0; nt < 4; nt++) {
                float* d = acc[mt][nt];
                const int r = wm + mt*16 + qr;
                const int c = wn + nt*8 + qc*2;
                *reinterpret_cast<float2*>(&stg[r * GRAM_LDS + c]) =
                    make_float2(d[0], d[1]);
                *reinterpret_cast<float2*>(&stg[(r+8) * GRAM_LDS + c]) =
                    make_float2(d[2], d[3]);
            }
        }
        __syncthreads();
        for (int v = tid; v < 128 * 32; v += 256) {
            const int cc = v & 127;
            const int r2 = (v >> 7) * 4;
            float4 t = *reinterpret_cast<const float4*>(&stg[cc * GRAM_LDS + r2]);
            float* ob = &Out[(size_t)(colBase + r2) * N_NODES + rowBase + cc];
            stg_cs_f1(ob,             t.x);
            stg_cs_f1(ob + N_NODES,   t.y);
            stg_cs_f1(ob + 2*N_NODES, t.z);
            stg_cs_f1(ob + 3*N_NODES, t.w);
        }
    }
}

// ---------------------------------------------------------------------------
extern "C" void kernel_launch(void* const* d_in, const int* in_sizes, int n_in,
                              void* d_out, int out_size)
{
    const float* x  = (const float*)d_in[0];
    const int*   ei = (const int*)  d_in[1];
    const float* W0 = (const float*)d_in[2];
    const float* b0 = (const float*)d_in[3];
    const float* W1 = (const float*)d_in[4];
    const float* b1 = (const float*)d_in[5];
    const float* W2 = (const float*)d_in[6];
    const float* b2 = (const float*)d_in[7];
    float* out = (float*)d_out;

    void *p_h0, *p_h1, *p_zn;
    cudaGetSymbolAddress(&p_h0, g_h0);
    cudaGetSymbolAddress(&p_h1, g_h1);
    cudaGetSymbolAddress(&p_zn, g_zn);
    float* h0 = (float*)p_h0;
    float* h1 = (float*)p_h1;
    float* zn = (float*)p_zn;

    cudaFuncSetAttribute(gram_mma_kernel,
                         cudaFuncAttributeMaxDynamicSharedMemorySize,
                         GRAM_SMEM_BYTES);

    zero_loss_kernel<<<1, 1>>>();

    // encoder (tensor cores, cp.async double-buffered; per-layer best tiles)
    gemm_mma_kernel<64,  128, true,  false><<<dim3(HID/128, N_NODES/64),  256>>>(
        x,  W0, b0, h0, D_IN, HID);
    gemm_mma_kernel<64,  128, true,  false><<<dim3(HID/128, N_NODES/64),  256>>>(
        h0, W1, b1, h1, HID,  HID);
    gemm_mma_kernel<128, 64,  false, true ><<<dim3(1,       N_NODES/128), 256>>>(
        h1, W2, b2, zn, HID,  D_OUT);

    // edge loss (restructured: 4 edges/warp, 8 lanes/edge)
    edge_loss_kernel<<<1024, 256>>>(ei, zn);

    // full similarity matrix (symmetric, tensor-core, 2D grid + early exit)
    gram_mma_kernel<<<dim3(N_NODES/128, N_NODES/128), 256, GRAM_SMEM_BYTES>>>(zn, out);

    // scalar loss at the end of the output buffer
    if ((long long)out_size > (long long)N_NODES * N_NODES)
        write_loss_kernel<<<1, 1>>>(out);
}

// round 17
// speedup vs baseline: 1.1077x; 1.0136x over previous
#include <cuda_runtime.h>
#include <math.h>
#include <stdint.h>

#define N_NODES 12288
#define D_IN    512
#define HID     256
#define D_OUT   64
#define E_EDGES 393216

// ---------------- scratch (device globals: no runtime allocation) ----------
__device__ float  g_h0[(size_t)N_NODES * HID];
__device__ float  g_h1[(size_t)N_NODES * HID];
__device__ float  g_zn[(size_t)N_NODES * D_OUT];
__device__ double g_loss_sum;

// ---------------------------------------------------------------------------
// tf32 / cp.async / sigmoid / streaming-store helpers
// ---------------------------------------------------------------------------
__device__ __forceinline__ uint32_t f32_to_tf32(float x) {
    uint32_t r;
    asm("cvt.rna.tf32.f32 %0, %1;" : "=r"(r) : "f"(x));
    return r;
}

__device__ __forceinline__ void mma_tf32(float d[4],
                                         const uint32_t a[4],
                                         const uint32_t b[2]) {
    asm volatile(
        "mma.sync.aligned.m16n8k8.row.col.f32.tf32.tf32.f32 "
        "{%0,%1,%2,%3}, {%4,%5,%6,%7}, {%8,%9}, {%0,%1,%2,%3};"
        : "+f"(d[0]), "+f"(d[1]), "+f"(d[2]), "+f"(d[3])
        : "r"(a[0]), "r"(a[1]), "r"(a[2]), "r"(a[3]),
          "r"(b[0]), "r"(b[1]));
}

__device__ __forceinline__ void cp_async16(float* smem_dst, const float* gmem_src) {
    uint32_t s = (uint32_t)__cvta_generic_to_shared(smem_dst);
    asm volatile("cp.async.cg.shared.global [%0], [%1], 16;"
                 :: "r"(s), "l"(gmem_src));
}
#define CP_COMMIT()      asm volatile("cp.async.commit_group;")
#define CP_WAIT(n)       asm volatile("cp.async.wait_group %0;" :: "n"(n))

__device__ __forceinline__ float fast_sigmoid(float x) {
    float t;
    asm("tanh.approx.f32 %0, %1;" : "=f"(t) : "f"(x * 0.5f));
    return fmaf(t, 0.5f, 0.5f);
}

__device__ __forceinline__ void stg_cs_f2(float* p, float a, float b) {
    asm volatile("st.global.cs.v2.f32 [%0], {%1,%2};"
                 :: "l"(p), "f"(a), "f"(b) : "memory");
}
__device__ __forceinline__ void stg_cs_f1(float* p, float a) {
    asm volatile("st.global.cs.f32 [%0], %1;" :: "l"(p), "f"(a) : "memory");
}

// ---------------------------------------------------------------------------
// Encoder GEMM on tensor cores, cp.async double-buffered (exact R16 config).
// ---------------------------------------------------------------------------
#define LDA 36

template<int BM, int BN, bool RELU, bool NORM>
__global__ __launch_bounds__(256)
void gemm_mma_kernel(const float* __restrict__ A,
                     const float* __restrict__ W,
                     const float* __restrict__ bias,
                     float* __restrict__ C,
                     int K, int Nn)
{
    constexpr int LDW = BN + 4;
    constexpr int WN  = BN / 32;
    constexpr int WM  = 8 / WN;
    constexpr int MT  = BM / (WM * 16);
    constexpr int NT  = 4;
    static_assert(MT >= 1, "bad BM/BN combo");

    constexpr int A_FLOATS = BM * LDA;
    constexpr int W_FLOATS = 32 * LDW;
    constexpr int NEED_MAIN = 2 * (A_FLOATS + W_FLOATS);
    constexpr int NEED_STG  = NORM ? BM * 68 : 0;
    constexpr int SMEM_FLOATS = NEED_MAIN > NEED_STG ? NEED_MAIN : NEED_STG;

    __shared__ float smem[SMEM_FLOATS];
    float* Asb[2] = { smem, smem + A_FLOATS + W_FLOATS };
    float* Wsb[2] = { smem + A_FLOATS, smem + 2*A_FLOATS + W_FLOATS };

    const int tid  = threadIdx.x;
    const int lane = tid & 31;
    const int wid  = tid >> 5;
    const int wm   = (wid / WN) * (MT * 16);
    const int wn   = (wid % WN) * 32;
    const int qr   = lane >> 2;
    const int qc   = lane & 3;
    const int rowBase = blockIdx.y * BM;
    const int colBase = blockIdx.x * BN;

    auto load_tiles = [&](int kk, int buf) {
        float* As = Asb[buf];
        float* Ws = Wsb[buf];
#pragma unroll
        for (int v = tid; v < BM * 8; v += 256) {
            const int r  = v >> 3;
            const int c4 = (v & 7) * 4;
            cp_async16(&As[r * LDA + c4],
                       &A[(size_t)(rowBase + r) * K + kk + c4]);
        }
#pragma unroll
        for (int v = tid; v < 32 * (BN/4); v += 256) {
            const int kr = v / (BN/4);
            const int n4 = (v % (BN/4)) * 4;
            cp_async16(&Ws[kr * LDW + n4],
                       &W[(size_t)(kk + kr) * Nn + colBase + n4]);
        }
        CP_COMMIT();
    };

    float acc[MT][NT][4];
#pragma unroll
    for (int mt = 0; mt < MT; mt++)
#pragma unroll
        for (int nt = 0; nt < NT; nt++)
#pragma unroll
            for (int i = 0; i < 4; i++) acc[mt][nt][i] = 0.f;

    load_tiles(0, 0);

    int buf = 0;
    for (int kk = 0; kk < K; kk += 32, buf ^= 1) {
        if (kk + 32 < K) {
            load_tiles(kk + 32, buf ^ 1);
            CP_WAIT(1);
        } else {
            CP_WAIT(0);
        }
        __syncthreads();

        const float* As = Asb[buf];
        const float* Ws = Wsb[buf];
#pragma unroll
        for (int k0 = 0; k0 < 32; k0 += 8) {
            uint32_t a[MT][4], b[NT][2];
#pragma unroll
            for (int mt = 0; mt < MT; mt++) {
                const float* base = &As[(wm + mt*16 + qr) * LDA + k0 + qc];
                a[mt][0] = f32_to_tf32(base[0]);
                a[mt][1] = f32_to_tf32(base[8 * LDA]);
                a[mt][2] = f32_to_tf32(base[4]);
                a[mt][3] = f32_to_tf32(base[8 * LDA + 4]);
            }
#pragma unroll
            for (int nt = 0; nt < NT; nt++) {
                const float* base = &Ws[(k0 + qc) * LDW + wn + nt*8 + qr];
                b[nt][0] = f32_to_tf32(base[0]);
                b[nt][1] = f32_to_tf32(base[4 * LDW]);
            }
#pragma unroll
            for (int mt = 0; mt < MT; mt++)
#pragma unroll
                for (int nt = 0; nt < NT; nt++)
                    mma_tf32(acc[mt][nt], a[mt], b[nt]);
        }
        __syncthreads();
    }

    if (!NORM) {
#pragma unroll
        for (int mt = 0; mt < MT; mt++) {
#pragma unroll
            for (int nt = 0; nt < NT; nt++) {
                float* d = acc[mt][nt];
                const int c = colBase + wn + nt*8 + qc*2;
                float bx = bias[c], by = bias[c+1];
                float2 lo = make_float2(d[0] + bx, d[1] + by);
                float2 hi = make_float2(d[2] + bx, d[3] + by);
                if (RELU) {
                    lo.x = fmaxf(lo.x, 0.f); lo.y = fmaxf(lo.y, 0.f);
                    hi.x = fmaxf(hi.x, 0.f); hi.y = fmaxf(hi.y, 0.f);
                }
                const size_t r0 = rowBase + wm + mt*16 + qr;
                *reinterpret_cast<float2*>(&C[r0 * Nn + c])     = lo;
                *reinterpret_cast<float2*>(&C[(r0+8) * Nn + c]) = hi;
            }
        }
    } else {
        constexpr int LDS = 68;
        float* stg = smem;
        __syncthreads();
#pragma unroll
        for (int mt = 0; mt < MT; mt++) {
#pragma unroll
            for (int nt = 0; nt < NT; nt++) {
                float* d = acc[mt][nt];
                const int c = wn + nt*8 + qc*2;
                float bx = bias[c], by = bias[c+1];
                const int r = wm + mt*16 + qr;
                *reinterpret_cast<float2*>(&stg[r * LDS + c]) =
                    make_float2(d[0] + bx, d[1] + by);
                *reinterpret_cast<float2*>(&stg[(r+8) * LDS + c]) =
                    make_float2(d[2] + bx, d[3] + by);
            }
        }
        __syncthreads();
#pragma unroll
        for (int rr = 0; rr < BM/8; rr++) {
            const int r = wid * (BM/8) + rr;
            float2 v = *reinterpret_cast<const float2*>(&stg[r * LDS + lane*2]);
            float ss = v.x*v.x + v.y*v.y;
#pragma unroll
            for (int o = 16; o > 0; o >>= 1)
                ss += __shfl_xor_sync(0xffffffffu, ss, o);
            float inv = rsqrtf(fmaxf(ss, 1e-30f));
            *reinterpret_cast<float2*>(&C[(size_t)(rowBase + r) * D_OUT + lane*2]) =
                make_float2(v.x * inv, v.y * inv);
        }
    }
}

// ---------------------------------------------------------------------------
// Edge reconstruction loss (R16 form: 4 edges/warp, 8 lanes/edge)
// ---------------------------------------------------------------------------
__global__ __launch_bounds__(256)
void edge_loss_kernel(const int* __restrict__ ei,
                      const float* __restrict__ Zn)
{
    const int lane = threadIdx.x & 31;
    const int wid  = threadIdx.x >> 5;
    const int g    = lane >> 3;
    const int l    = lane & 7;
    const int gw   = blockIdx.x * 8 + wid;
    const int nw   = gridDim.x * 8;

    float lsum = 0.f;
    for (int e0 = gw * 4; e0 < E_EDGES; e0 += nw * 4) {
        const int e = e0 + g;
        const int s = ei[e];
        const int d = ei[E_EDGES + e];
        const float4* sp = reinterpret_cast<const float4*>(&Zn[(size_t)s * D_OUT + l*8]);
        const float4* dp = reinterpret_cast<const float4*>(&Zn[(size_t)d * D_OUT + l*8]);
        float4 a0 = sp[0], a1 = sp[1];
        float4 b0 = dp[0], b1 = dp[1];
        float p = a0.x*b0.x + a0.y*b0.y + a0.z*b0.z + a0.w*b0.w
                + a1.x*b1.x + a1.y*b1.y + a1.z*b1.z + a1.w*b1.w;
        p += __shfl_xor_sync(0xffffffffu, p, 4);
        p += __shfl_xor_sync(0xffffffffu, p, 2);
        p += __shfl_xor_sync(0xffffffffu, p, 1);
        if (l == 0) lsum += log1pf(__expf(-p));
    }

#pragma unroll
    for (int o = 16; o > 0; o >>= 1)
        lsum += __shfl_xor_sync(0xffffffffu, lsum, o);

    __shared__ float wsum[8];
    if (lane == 0) wsum[wid] = lsum;
    __syncthreads();
    if (threadIdx.x == 0) {
        float t = 0.f;
#pragma unroll
        for (int i = 0; i < 8; i++) t += wsum[i];
        atomicAdd(&g_loss_sum, (double)t);
    }
}

__global__ void zero_loss_kernel() { g_loss_sum = 0.0; }

__global__ void write_loss_kernel(float* __restrict__ out)
{
    out[(size_t)N_NODES * N_NODES] = (float)(g_loss_sum / (double)E_EDGES);
}

// ---------------------------------------------------------------------------
// Gram + sigmoid via tf32 mma (exact R16 measured-best structure)
// ---------------------------------------------------------------------------
#define GRAM_LDK  68
#define GRAM_LDS  132
#define GRAM_SMEM_BYTES (2 * 128 * GRAM_LDK * 4)   // 69,632 B

__global__ __launch_bounds__(256)
void gram_mma_kernel(const float* __restrict__ Z, float* __restrict__ Out)
{
    extern __shared__ float smem[];
    float* As = smem;
    float* Bs = smem + 128 * GRAM_LDK;

    const int bi = blockIdx.y;
    const int bj = blockIdx.x;
    if (bj < bi) return;
    const int rowBase = bi * 128;
    const int colBase = bj * 128;

    const int tid  = threadIdx.x;
    const int lane = tid & 31;
    const int wid  = tid >> 5;
    const int wm   = (wid >> 2) * 64;
    const int wn   = (wid & 3) * 32;
    const int qr   = lane >> 2;
    const int qc   = lane & 3;

    for (int v = tid; v < 128 * 16; v += 256) {
        const int r  = v >> 4;
        const int c4 = (v & 15) * 4;
        cp_async16(&As[r * GRAM_LDK + c4],
                   &Z[(size_t)(rowBase + r) * D_OUT + c4]);
    }
    if (bj != bi) {
        for (int v = tid; v < 128 * 16; v += 256) {
            const int r  = v >> 4;
            const int c4 = (v & 15) * 4;
            cp_async16(&Bs[r * GRAM_LDK + c4],
                       &Z[(size_t)(colBase + r) * D_OUT + c4]);
        }
    }
    CP_COMMIT();
    CP_WAIT(0);
    __syncthreads();

    const float* Bp = (bj == bi) ? As : Bs;

    float acc[4][4][4];
#pragma unroll
    for (int mt = 0; mt < 4; mt++)
#pragma unroll
        for (int nt = 0; nt < 4; nt++)
#pragma unroll
            for (int i = 0; i < 4; i++) acc[mt][nt][i] = 0.f;

#pragma unroll
    for (int k0 = 0; k0 < D_OUT; k0 += 8) {
        uint32_t a[4][4], b[4][2];
#pragma unroll
        for (int mt = 0; mt < 4; mt++) {
            const float* base = &As[(wm + mt*16 + qr) * GRAM_LDK + k0 + qc];
            a[mt][0] = f32_to_tf32(base[0]);
            a[mt][1] = f32_to_tf32(base[8 * GRAM_LDK]);
            a[mt][2] = f32_to_tf32(base[4]);
            a[mt][3] = f32_to_tf32(base[8 * GRAM_LDK + 4]);
        }
#pragma unroll
        for (int nt = 0; nt < 4; nt++) {
            const float* base = &Bp[(wn + nt*8 + qr) * GRAM_LDK + k0 + qc];
            b[nt][0] = f32_to_tf32(base[0]);
            b[nt][1] = f32_to_tf32(base[4]);
        }
#pragma unroll
        for (int mt = 0; mt < 4; mt++)
#pragma unroll
            for (int nt = 0; nt < 4; nt++)
                mma_tf32(acc[mt][nt], a[mt], b[nt]);
    }

#pragma unroll
    for (int mt = 0; mt < 4; mt++) {
#pragma unroll
        for (int nt = 0; nt < 4; nt++) {
            float* d = acc[mt][nt];
            d[0] = fast_sigmoid(d[0]);
            d[1] = fast_sigmoid(d[1]);
            d[2] = fast_sigmoid(d[2]);
            d[3] = fast_sigmoid(d[3]);
            const size_t r = rowBase + wm + mt*16 + qr;
            const int    c = colBase + wn + nt*8 + qc*2;
            stg_cs_f2(&Out[r * N_NODES + c],     d[0], d[1]);
            stg_cs_f2(&Out[(r+8) * N_NODES + c], d[2], d[3]);
        }
    }

    if (bj > bi) {
        __syncthreads();
        float* stg = smem;
#pragma unroll
        for (int mt = 0; mt < 4; mt++) {
#pragma unroll
            for (int nt = 0; nt < 4; nt++) {
                float* d = acc[mt][nt];
                const int r = wm + mt*16 + qr;
                const int c = wn + nt*8 + qc*2;
                *reinterpret_cast<float2*>(&stg[r * GRAM_LDS + c]) =
                    make_float2(d[0], d[1]);
                *reinterpret_cast<float2*>(&stg[(r+8) * GRAM_LDS + c]) =
                    make_float2(d[2], d[3]);
            }
        }
        __syncthreads();
        for (int v = tid; v < 128 * 32; v += 256) {
            const int cc = v & 127;
            const int r2 = (v >> 7) * 4;
            float4 t = *reinterpret_cast<const float4*>(&stg[cc * GRAM_LDS + r2]);
            float* ob = &Out[(size_t)(colBase + r2) * N_NODES + rowBase + cc];
            stg_cs_f1(ob,             t.x);
            stg_cs_f1(ob + N_NODES,   t.y);
            stg_cs_f1(ob + 2*N_NODES, t.z);
            stg_cs_f1(ob + 3*N_NODES, t.w);
        }
    }
}

// ---------------------------------------------------------------------------
extern "C" void kernel_launch(void* const* d_in, const int* in_sizes, int n_in,
                              void* d_out, int out_size)
{
    const float* x  = (const float*)d_in[0];
    const int*   ei = (const int*)  d_in[1];
    const float* W0 = (const float*)d_in[2];
    const float* b0 = (const float*)d_in[3];
    const float* W1 = (const float*)d_in[4];
    const float* b1 = (const float*)d_in[5];
    const float* W2 = (const float*)d_in[6];
    const float* b2 = (const float*)d_in[7];
    float* out = (float*)d_out;

    void *p_h0, *p_h1, *p_zn;
    cudaGetSymbolAddress(&p_h0, g_h0);
    cudaGetSymbolAddress(&p_h1, g_h1);
    cudaGetSymbolAddress(&p_zn, g_zn);
    float* h0 = (float*)p_h0;
    float* h1 = (float*)p_h1;
    float* zn = (float*)p_zn;

    cudaFuncSetAttribute(gram_mma_kernel,
                         cudaFuncAttributeMaxDynamicSharedMemorySize,
                         GRAM_SMEM_BYTES);

    // side stream + events for edge||gram overlap (host objects only; no
    // device memory; created fresh each call -> no static guards)
    cudaStream_t s_edge;
    cudaStreamCreateWithFlags(&s_edge, cudaStreamNonBlocking);
    cudaEvent_t ev_fork, ev_join;
    cudaEventCreateWithFlags(&ev_fork, cudaEventDisableTiming);
    cudaEventCreateWithFlags(&ev_join, cudaEventDisableTiming);

    zero_loss_kernel<<<1, 1>>>();

    // encoder (tensor cores, cp.async double-buffered; per-layer best tiles)
    gemm_mma_kernel<64,  128, true,  false><<<dim3(HID/128, N_NODES/64),  256>>>(
        x,  W0, b0, h0, D_IN, HID);
    gemm_mma_kernel<64,  128, true,  false><<<dim3(HID/128, N_NODES/64),  256>>>(
        h0, W1, b1, h1, HID,  HID);
    gemm_mma_kernel<128, 64,  false, true ><<<dim3(1,       N_NODES/128), 256>>>(
        h1, W2, b2, zn, HID,  D_OUT);

    // fork: edge loss runs concurrently with the gram on a side stream
    cudaEventRecord(ev_fork, 0);
    cudaStreamWaitEvent(s_edge, ev_fork, 0);
    edge_loss_kernel<<<1024, 256, 0, s_edge>>>(ei, zn);
    cudaEventRecord(ev_join, s_edge);

    // gram proceeds immediately on the main stream (independent of edge)
    gram_mma_kernel<<<dim3(N_NODES/128, N_NODES/128), 256, GRAM_SMEM_BYTES>>>(zn, out);

    // join edge results before the scalar loss write
    cudaStreamWaitEvent(0, ev_join, 0);
    if ((long long)out_size > (long long)N_NODES * N_NODES)
        write_loss_kernel<<<1, 1>>>(out);

    // release host-side objects (safe during capture: not captured ops)
    cudaEventDestroy(ev_fork);
    cudaEventDestroy(ev_join);
    cudaStreamDestroy(s_edge);
}